// round 5
// baseline (speedup 1.0000x reference)
#include <cuda_runtime.h>
#include <cuda_bf16.h>

#define T_STEPS 4096
#define BATCH   256
#define HID     32
#define G3      96

// Scratch. g_xg layout: [t][gate][j]; r,z entries pre-scaled by 0.5 with both
// biases folded; n entries carry b_ih only. Padded 2 steps for prefetch.
__device__ float g_xg[(T_STEPS + 2) * G3];
__device__ float g_hs[T_STEPS * HID];

// ---------------------------------------------------------------------------
// f32x2 helpers (sm_100+)
// ---------------------------------------------------------------------------
__device__ __forceinline__ unsigned long long ffma2(unsigned long long a,
                                                    unsigned long long b,
                                                    unsigned long long c) {
    unsigned long long d;
    asm("fma.rn.f32x2 %0, %1, %2, %3;" : "=l"(d) : "l"(a), "l"(b), "l"(c));
    return d;
}
__device__ __forceinline__ unsigned long long add2(unsigned long long a,
                                                   unsigned long long b) {
    unsigned long long d;
    asm("add.rn.f32x2 %0, %1, %2;" : "=l"(d) : "l"(a), "l"(b));
    return d;
}
__device__ __forceinline__ unsigned long long mul2(unsigned long long a,
                                                   unsigned long long b) {
    unsigned long long d;
    asm("mul.rn.f32x2 %0, %1, %2;" : "=l"(d) : "l"(a), "l"(b));
    return d;
}
__device__ __forceinline__ unsigned long long pack2(float lo, float hi) {
    unsigned long long d;
    asm("mov.b64 %0, {%1, %2};"
        : "=l"(d) : "r"(__float_as_uint(lo)), "r"(__float_as_uint(hi)));
    return d;
}
__device__ __forceinline__ float fold2(unsigned long long a) {
    unsigned int lo, hi;
    asm("mov.b64 {%0, %1}, %2;" : "=r"(lo), "=r"(hi) : "l"(a));
    return __uint_as_float(lo) + __uint_as_float(hi);
}
__device__ __forceinline__ float tanh_a(float x) {
    float y;
    asm("tanh.approx.f32 %0, %1;" : "=f"(y) : "f"(x));
    return y;
}

// ---------------------------------------------------------------------------
// Kernel 1: xg precompute for batch row 255.
// g <  64 (r,z): 0.5 * (b_ih + b_hh + W x)   [pre-scaled for tanh-sigmoid]
// g >= 64 (n) :        (b_ih        + W x)   [b_hh_n stays inside hn]
// ---------------------------------------------------------------------------
__global__ void precompute_xg(const float* __restrict__ x,
                              const float* __restrict__ w_ih,
                              const float* __restrict__ b_ih,
                              const float* __restrict__ b_hh) {
    int idx = blockIdx.x * blockDim.x + threadIdx.x;
    if (idx >= T_STEPS * G3) return;
    int t = idx / G3;
    int g = idx - t * G3;
    float x0 = __ldg(&x[t * (BATCH * 2) + (BATCH - 1) * 2 + 0]);
    float x1 = __ldg(&x[t * (BATCH * 2) + (BATCH - 1) * 2 + 1]);
    float v = b_ih[g] + w_ih[g * 2 + 0] * x0 + w_ih[g * 2 + 1] * x1;
    if (g < 2 * HID) v = 0.5f * (v + b_hh[g]);
    g_xg[t * G3 + g] = v;
}

// ---------------------------------------------------------------------------
// Kernel 2: sequential GRU. 3 warps (gate each), one bar/step, redundant
// finisher, no syncwarp (warp-uniform control flow; LSU keeps same-warp
// smem program order; compiler fence stops reordering).
// ---------------------------------------------------------------------------
__global__ void __launch_bounds__(G3, 1)
gru_seq(const float* __restrict__ w_hh, const float* __restrict__ b_hh) {
    __shared__ __align__(16) float h_priv[3][HID];   // per-warp h copy
    __shared__ float sh_r [2][HID];                  // double-buffered stages
    __shared__ float sh_z [2][HID];
    __shared__ float sh_hn[2][HID];
    __shared__ float sh_xn[2][HID];

    const int w = threadIdx.x >> 5;      // warp = gate (0:r, 1:z, 2:n)
    const int j = threadIdx.x & 31;      // lane = hidden unit / row

    // 16 packed weight pairs (row w*32+j); r,z rows pre-scaled by 0.5.
    unsigned long long wk[16];
    const unsigned long long* W = (const unsigned long long*)w_hh;
#pragma unroll
    for (int p = 0; p < 16; p++) wk[p] = W[(w * HID + j) * 16 + p];
    if (w < 2) {
        const unsigned long long half2 = pack2(0.5f, 0.5f);
#pragma unroll
        for (int p = 0; p < 16; p++) wk[p] = mul2(wk[p], half2);
    }
    const float bn = b_hh[2 * HID + j];  // used by w==2 only

    h_priv[w][j] = 0.0f;
    float h_old = 0.0f;

    // Depth-2 register prefetch of this warp's gate column (L2-resident).
    const float* xs = g_xg + w * HID + j;
    float xc = xs[0 * G3];
    float x1 = xs[1 * G3];
    __syncthreads();

#pragma unroll 2
    for (int t = 0; t < T_STEPS; t++) {
        const int p = t & 1;
        float x2 = xs[(t + 2) * G3];               // prefetch t+2

        if (w == 2) sh_xn[p][j] = xc;              // stage xn early (reg-ready)

        // ---- pre = init + W_row . h  (4 accumulators, LDS.128 broadcast) ----
        unsigned long long a0 = pack2((w == 2) ? bn : xc, 0.0f);
        unsigned long long a1 = pack2(0.0f, 0.0f);
        unsigned long long a2 = a1, a3 = a1;
        const ulonglong2* hp = (const ulonglong2*)h_priv[w];
#pragma unroll
        for (int i = 0; i < 4; i++) {
            ulonglong2 hq = hp[i];
            a0 = ffma2(wk[2 * i + 0], hq.x, a0);
            a1 = ffma2(wk[2 * i + 1], hq.y, a1);
        }
#pragma unroll
        for (int i = 4; i < 8; i++) {
            ulonglong2 hq = hp[i];
            a2 = ffma2(wk[2 * i + 0], hq.x, a2);
            a3 = ffma2(wk[2 * i + 1], hq.y, a3);
        }
        float pre = fold2(add2(add2(a0, a1), add2(a2, a3)));

        if (w == 0)      sh_r[p][j] = fmaf(tanh_a(pre), 0.5f, 0.5f);
        else if (w == 1) sh_z[p][j] = fmaf(tanh_a(pre), 0.5f, 0.5f);
        else             sh_hn[p][j] = pre;
        __syncthreads();                           // the one block barrier

        // ---- redundant finish in every warp ----
        float z  = sh_z [p][j];
        float r  = sh_r [p][j];
        float hn = sh_hn[p][j];
        float xn = sh_xn[p][j];
        float u  = z * h_old;                      // runs under tanh latency
        float v  = 1.0f - z;
        float n  = tanh_a(fmaf(r, hn, xn));
        float h  = fmaf(n, v, u);                  // (1-z)*n + z*h_old
        h_old = h;
        h_priv[w][j] = h;
        if (w == 0) g_hs[t * HID + j] = h;         // fire-and-forget
        asm volatile("" ::: "memory");             // keep STS before next LDS

        xc = x1; x1 = x2;
    }
}

// ---------------------------------------------------------------------------
// Kernel 3: out[t] = b_fc + w_fc . h_t  (warp per timestep)
// ---------------------------------------------------------------------------
__global__ void fc_kernel(const float* __restrict__ w_fc,
                          const float* __restrict__ b_fc,
                          float* __restrict__ out) {
    int t = blockIdx.x;
    int j = threadIdx.x;
    float v = w_fc[j] * g_hs[t * HID + j];
#pragma unroll
    for (int off = 16; off > 0; off >>= 1)
        v += __shfl_xor_sync(0xFFFFFFFFu, v, off);
    if (j == 0) out[t] = v + b_fc[0];
}

// ---------------------------------------------------------------------------
extern "C" void kernel_launch(void* const* d_in, const int* in_sizes, int n_in,
                              void* d_out, int out_size) {
    const float* x    = (const float*)d_in[0];
    const float* w_ih = (const float*)d_in[1];
    const float* w_hh = (const float*)d_in[2];
    const float* b_ih = (const float*)d_in[3];
    const float* b_hh = (const float*)d_in[4];
    const float* w_fc = (const float*)d_in[5];
    const float* b_fc = (const float*)d_in[6];
    float* out = (float*)d_out;

    precompute_xg<<<(T_STEPS * G3 + 255) / 256, 256>>>(x, w_ih, b_ih, b_hh);
    gru_seq<<<1, G3>>>(w_hh, b_hh);
    fc_kernel<<<T_STEPS, HID>>>(w_fc, b_fc, out);
}